// round 3
// baseline (speedup 1.0000x reference)
#include <cuda_runtime.h>
#include <cuda_bf16.h>
#include <mma.h>
#include <cstdint>
#include <cstddef>
#include <math.h>

using namespace nvcuda;

#define S_LEN 128
#define BATCH 16
#define HID   1024
#define G4    4096
#define ROWS  2048            // S*B
#define WS_LD 1032            // padded smem leading dim (mult of 8)
#define PASS_SMEM_BYTES ((32*WS_LD + 16*WS_LD + 8*576) * 4)   // 216576
#define GEMM_SMEM_BYTES ((2560 + 2560 + 16384) * 4)           // 86016

// ---------------- static device scratch (no cudaMalloc anywhere) -------------
__device__ __align__(16) float d_X [ROWS*HID];
__device__ __align__(16) float d_G0[ROWS*G4];
__device__ __align__(16) float d_G1[ROWS*G4];
__device__ __align__(16) float d_Y0[ROWS*HID];
__device__ __align__(16) float d_D0[ROWS*HID];
__device__ __align__(16) float d_D1[ROWS*HID];
__device__ __align__(16) float d_hbuf[BATCH*HID];
__device__ __align__(16) float d_gbuf[BATCH*G4];
__device__ __align__(16) float d_he0[BATCH*HID];
__device__ __align__(16) float d_ce0[BATCH*HID];
__device__ __align__(16) float d_he1[BATCH*HID];
__device__ __align__(16) float d_ce1[BATCH*HID];
__device__ __align__(16) float d_dh0[BATCH*HID];
__device__ __align__(16) float d_dh1[BATCH*HID];
__device__ __align__(16) float d_zeros[BATCH*HID];
__device__ __align__(16) float d_bc0[G4];
__device__ __align__(16) float d_bc1[G4];
__device__ int d_gdone[4];
__device__ int d_hdone[4];

__device__ __forceinline__ float sigf(float x) { return 1.0f / (1.0f + expf(-x)); }

// ---------------- init: reset sync counters, combine biases, zero state ------
__global__ void init_kernel(const float* __restrict__ bih0, const float* __restrict__ bhh0,
                            const float* __restrict__ bih1, const float* __restrict__ bhh1) {
    int tid = blockIdx.x * blockDim.x + threadIdx.x;   // 4096 threads
    if (tid < 4) { d_gdone[tid] = 0; d_hdone[tid] = 0; }
    for (int i = tid; i < BATCH*HID; i += 4096) d_zeros[i] = 0.0f;
    if (tid < G4) {
        d_bc0[tid] = bih0[tid] + bhh0[tid];
        d_bc1[tid] = bih1[tid] + bhh1[tid];
    }
}

// ---------------- embedding gather: X[row] = emb[tokens[row]] ----------------
__global__ void embed_kernel(const int* __restrict__ tokens, const float* __restrict__ emb) {
    int row = blockIdx.x;                              // 0..2047 = t*B + b
    int tok = tokens[row];
    const float4* src = (const float4*)(emb + (size_t)tok * HID);
    float4* dst = (float4*)(d_X + (size_t)row * HID);
    for (int i = threadIdx.x; i < HID/4; i += blockDim.x) dst[i] = src[i];
}

// ---------------- tf32 WMMA GEMM: C[M,N] = A[M,K] @ B[N,K]^T + bias[N] -------
// grid = (M/128, N/128), block = 256 (8 warps; warp tile 32x64)
__global__ void __launch_bounds__(256) gemm_tf32_bias(
    const float* __restrict__ A, const float* __restrict__ B,
    const float* __restrict__ bias, float* __restrict__ C, int N, int K)
{
    extern __shared__ float smg[];
    float* As = smg;                 // [128][20]
    float* Bs = smg + 2560;          // [128][20]
    float* wb = smg + 5120;          // 8 warps x [32][64]
    const int tid = threadIdx.x;
    const int m0 = blockIdx.x * 128;
    const int n0 = blockIdx.y * 128;
    const int w  = tid >> 5;
    const int lane = tid & 31;
    const int wm = w & 3;            // 4 warps along M
    const int wn = w >> 2;           // 2 warps along N

    wmma::fragment<wmma::accumulator, 16, 16, 8, float> acc[2][4];
#pragma unroll
    for (int mi = 0; mi < 2; mi++)
#pragma unroll
        for (int nj = 0; nj < 4; nj++) wmma::fill_fragment(acc[mi][nj], 0.0f);

    for (int k0 = 0; k0 < K; k0 += 16) {
#pragma unroll
        for (int i = 0; i < 2; i++) {
            int idx = tid + i * 256;           // 0..511
            int row = idx >> 2;
            int c4  = idx & 3;
            float4 av = ((const float4*)(A + (size_t)(m0 + row) * K + k0))[c4];
            av.x = wmma::__float_to_tf32(av.x); av.y = wmma::__float_to_tf32(av.y);
            av.z = wmma::__float_to_tf32(av.z); av.w = wmma::__float_to_tf32(av.w);
            ((float4*)(As + row * 20))[0] = av; // placeholder to keep alignment; overwritten below
            // store at proper column offset
            float* ap = As + row * 20 + c4 * 4;
            ap[0] = av.x; ap[1] = av.y; ap[2] = av.z; ap[3] = av.w;
            float4 bv = ((const float4*)(B + (size_t)(n0 + row) * K + k0))[c4];
            bv.x = wmma::__float_to_tf32(bv.x); bv.y = wmma::__float_to_tf32(bv.y);
            bv.z = wmma::__float_to_tf32(bv.z); bv.w = wmma::__float_to_tf32(bv.w);
            float* bp = Bs + row * 20 + c4 * 4;
            bp[0] = bv.x; bp[1] = bv.y; bp[2] = bv.z; bp[3] = bv.w;
        }
        __syncthreads();
#pragma unroll
        for (int kk = 0; kk < 16; kk += 8) {
            wmma::fragment<wmma::matrix_a, 16, 16, 8, wmma::precision::tf32, wmma::row_major> fa[2];
            wmma::fragment<wmma::matrix_b, 16, 16, 8, wmma::precision::tf32, wmma::col_major> fb[4];
#pragma unroll
            for (int mi = 0; mi < 2; mi++)
                wmma::load_matrix_sync(fa[mi], As + (wm * 32 + mi * 16) * 20 + kk, 20);
#pragma unroll
            for (int nj = 0; nj < 4; nj++)
                wmma::load_matrix_sync(fb[nj], Bs + (wn * 64 + nj * 16) * 20 + kk, 20);
#pragma unroll
            for (int mi = 0; mi < 2; mi++)
#pragma unroll
                for (int nj = 0; nj < 4; nj++)
                    wmma::mma_sync(acc[mi][nj], fa[mi], fb[nj], acc[mi][nj]);
        }
        __syncthreads();
    }

    // epilogue: per-warp smem buffer (warp-private), bias add, coalesced stores
    float* myb = wb + w * 2048;
#pragma unroll
    for (int mi = 0; mi < 2; mi++)
#pragma unroll
        for (int nj = 0; nj < 4; nj++)
            wmma::store_matrix_sync(myb + mi * 1024 + nj * 16, acc[mi][nj], 64, wmma::mem_row_major);
    __syncwarp();
#pragma unroll 8
    for (int i = 0; i < 64; i++) {
        int idx = i * 32 + lane;       // 0..2047
        int r = idx >> 6;              // 0..31
        int c = idx & 63;              // 0..63
        float v = myb[r * 64 + c] + bias[n0 + wn * 64 + c];
        C[(size_t)(m0 + wm * 32 + r) * N + n0 + wn * 64 + c] = v;
    }
}

// ---------------- persistent LSTM layer pass ---------------------------------
// 128 CTAs, 1/SM (all co-resident). CTA n owns gate cols [32n,32n+32); its 32
// Whh rows live in SMEM for all 128 steps. CTAs 0..31 own hidden units
// [32n,32n+32) for the elementwise update (cell state in registers).
__global__ void __launch_bounds__(256, 1) lstm_pass(
    const float* __restrict__ Gpre, const float* __restrict__ Whh,
    const float* __restrict__ h0, const float* __restrict__ c0,
    float* __restrict__ y, float* __restrict__ hout, float* __restrict__ cout, int pass)
{
    extern __shared__ float sm[];
    float* ws  = sm;                       // [32][WS_LD]  weights (tf32-rounded)
    float* hs  = sm + 32 * WS_LD;          // [16][WS_LD]  h staging
    float* red = sm + 48 * WS_LD;          // 8 warps x [16][36]
    const int tid = threadIdx.x;
    const int cta = blockIdx.x;
    const int w   = tid >> 5;

    // load this CTA's 32x1024 weight slice once, pre-rounded to tf32
    {
        const float4* src = (const float4*)(Whh + (size_t)cta * 32 * HID);
        for (int i = tid; i < 32 * 256; i += 256) {
            int r = i >> 8, c = i & 255;
            float4 v = src[i];
            v.x = wmma::__float_to_tf32(v.x); v.y = wmma::__float_to_tf32(v.y);
            v.z = wmma::__float_to_tf32(v.z); v.w = wmma::__float_to_tf32(v.w);
            ((float4*)(ws + r * WS_LD))[c] = v;
        }
    }
    __syncthreads();

    volatile int* vg = (volatile int*)&d_gdone[pass];
    volatile int* vh = (volatile int*)&d_hdone[pass];

    // cell state registers for owner CTAs: 2 (b,u) pairs per thread
    float creg[2] = {0.0f, 0.0f};
    if (cta < 32) {
#pragma unroll
        for (int q = 0; q < 2; q++) {
            int idx = tid * 2 + q;             // 0..511
            creg[q] = c0[(idx >> 5) * HID + cta * 32 + (idx & 31)];
        }
    }

#pragma unroll 1
    for (int t = 0; t < S_LEN; t++) {
        // ---- phase A: wait h[t-1], stage to smem (tf32), matmul, publish gates
        if (t > 0) { if (tid == 0) { while (*vh < 32 * t) { } } }
        __syncthreads();
        __threadfence();
        {
            const float4* src = (const float4*)(t == 0 ? h0 : (const float*)d_hbuf);
            for (int i = tid; i < 16 * 256; i += 256) {
                int r = i >> 8, c = i & 255;
                float4 v = src[i];
                v.x = wmma::__float_to_tf32(v.x); v.y = wmma::__float_to_tf32(v.y);
                v.z = wmma::__float_to_tf32(v.z); v.w = wmma::__float_to_tf32(v.w);
                ((float4*)(hs + r * WS_LD))[c] = v;
            }
        }
        __syncthreads();

        // warp w handles K slice [w*128, (w+1)*128)
        {
            wmma::fragment<wmma::accumulator, 16, 16, 8, float> a0, a1;
            wmma::fill_fragment(a0, 0.0f);
            wmma::fill_fragment(a1, 0.0f);
#pragma unroll
            for (int kk = 0; kk < 128; kk += 8) {
                int k = w * 128 + kk;
                wmma::fragment<wmma::matrix_a, 16, 16, 8, wmma::precision::tf32, wmma::row_major> fa;
                wmma::fragment<wmma::matrix_b, 16, 16, 8, wmma::precision::tf32, wmma::col_major> f0, f1;
                wmma::load_matrix_sync(fa, hs + k, WS_LD);
                wmma::load_matrix_sync(f0, ws + k, WS_LD);
                wmma::load_matrix_sync(f1, ws + 16 * WS_LD + k, WS_LD);
                wmma::mma_sync(a0, fa, f0, a0);
                wmma::mma_sync(a1, fa, f1, a1);
            }
            wmma::store_matrix_sync(red + w * 576,      a0, 36, wmma::mem_row_major);
            wmma::store_matrix_sync(red + w * 576 + 16, a1, 36, wmma::mem_row_major);
        }
        __syncthreads();

        // cross-warp reduce (8 partials), add precomputed input gates, publish
#pragma unroll
        for (int q = 0; q < 2; q++) {
            int idx = tid * 2 + q;               // 0..511
            int b = idx >> 5, u = idx & 31;
            float s = 0.0f;
#pragma unroll
            for (int p = 0; p < 8; p++) s += red[p * 576 + b * 36 + u];
            s += Gpre[(size_t)t * BATCH * G4 + b * G4 + cta * 32 + u];
            d_gbuf[b * G4 + cta * 32 + u] = s;
        }
        __threadfence();
        __syncthreads();
        if (tid == 0) atomicAdd(&d_gdone[pass], 1);

        // ---- phase B: owner CTAs apply LSTM elementwise, publish h[t] -------
        if (cta < 32) {
            if (tid == 0) { while (*vg < 128 * (t + 1)) { } }
            __syncthreads();
            __threadfence();
#pragma unroll
            for (int q = 0; q < 2; q++) {
                int idx = tid * 2 + q;
                int b = idx >> 5, u = idx & 31;
                int j = cta * 32 + u;
                float gi = d_gbuf[b * G4 + j];
                float gf = d_gbuf[b * G4 + HID + j];
                float gg = d_gbuf[b * G4 + 2 * HID + j];
                float go = d_gbuf[b * G4 + 3 * HID + j];
                float c = sigf(gf) * creg[q] + sigf(gi) * tanhf(gg);
                float h = sigf(go) * tanhf(c);
                creg[q] = c;
                d_hbuf[b * HID + j] = h;
                y[(size_t)t * BATCH * HID + b * HID + j] = h;
                if (t == S_LEN - 1) { hout[b * HID + j] = h; cout[b * HID + j] = c; }
            }
            __threadfence();
            __syncthreads();
            if (tid == 0) atomicAdd(&d_hdone[pass], 1);
        }
    }
}

// ---------------- latent linear: dh = he @ latW^T + latb (fp32 exact) --------
// grid 2048: block handles (which, batch, group of 16 cols)
__global__ void latent_kernel(const float* __restrict__ latW, const float* __restrict__ latb) {
    __shared__ float hesh[HID];
    int blk = blockIdx.x;
    int which = blk >> 10;
    int rem = blk & 1023;
    int b = rem >> 6;
    int jg = rem & 63;
    const float* he = which ? d_he1 : d_he0;
    float* dh = which ? d_dh1 : d_dh0;
    for (int i = threadIdx.x; i < HID; i += 256) hesh[i] = he[b * HID + i];
    __syncthreads();
    int w = threadIdx.x >> 5, lane = threadIdx.x & 31;
#pragma unroll
    for (int q = 0; q < 2; q++) {
        int j = jg * 16 + w * 2 + q;
        const float* wr = latW + (size_t)j * HID;
        float s = 0.0f;
        for (int k = lane; k < HID; k += 32) s += wr[k] * hesh[k];
#pragma unroll
        for (int o = 16; o; o >>= 1) s += __shfl_xor_sync(0xFFFFFFFFu, s, o);
        if (lane == 0) dh[b * HID + j] = s + latb[j];
    }
}

// ---------------- host orchestration -----------------------------------------
extern "C" void kernel_launch(void* const* d_in, const int* in_sizes, int n_in,
                              void* d_out, int out_size) {
    const int*   tokens   = (const int*)  d_in[0];
    const float* emb      = (const float*)d_in[1];
    const float* dec_bias = (const float*)d_in[2];
    const float* Wih0     = (const float*)d_in[3];
    const float* Whh0     = (const float*)d_in[4];
    const float* bih0     = (const float*)d_in[5];
    const float* bhh0     = (const float*)d_in[6];
    const float* Wih1     = (const float*)d_in[7];
    const float* Whh1     = (const float*)d_in[8];
    const float* bih1     = (const float*)d_in[9];
    const float* bhh1     = (const float*)d_in[10];
    const float* latW     = (const float*)d_in[11];
    const float* latb     = (const float*)d_in[12];
    float* out = (float*)d_out;

    cudaFuncSetAttribute(gemm_tf32_bias, cudaFuncAttributeMaxDynamicSharedMemorySize, GEMM_SMEM_BYTES);
    cudaFuncSetAttribute(lstm_pass,      cudaFuncAttributeMaxDynamicSharedMemorySize, PASS_SMEM_BYTES);

    float *pX, *pG0, *pG1, *pY0, *pD0, *pD1, *pZ, *pbc0, *pbc1;
    float *phe0, *pce0, *phe1, *pce1, *pdh0, *pdh1;
    cudaGetSymbolAddress((void**)&pX,   d_X);
    cudaGetSymbolAddress((void**)&pG0,  d_G0);
    cudaGetSymbolAddress((void**)&pG1,  d_G1);
    cudaGetSymbolAddress((void**)&pY0,  d_Y0);
    cudaGetSymbolAddress((void**)&pD0,  d_D0);
    cudaGetSymbolAddress((void**)&pD1,  d_D1);
    cudaGetSymbolAddress((void**)&pZ,   d_zeros);
    cudaGetSymbolAddress((void**)&pbc0, d_bc0);
    cudaGetSymbolAddress((void**)&pbc1, d_bc1);
    cudaGetSymbolAddress((void**)&phe0, d_he0);
    cudaGetSymbolAddress((void**)&pce0, d_ce0);
    cudaGetSymbolAddress((void**)&phe1, d_he1);
    cudaGetSymbolAddress((void**)&pce1, d_ce1);
    cudaGetSymbolAddress((void**)&pdh0, d_dh0);
    cudaGetSymbolAddress((void**)&pdh1, d_dh1);

    init_kernel<<<16, 256>>>(bih0, bhh0, bih1, bhh1);
    embed_kernel<<<ROWS, 256>>>(tokens, emb);

    // G0 = X @ Wih0^T + (bih0+bhh0)   [2048,4096]   (shared by enc-l0 & dec-l0)
    gemm_tf32_bias<<<dim3(16, 32), 256, GEMM_SMEM_BYTES>>>(pX, Wih0, pbc0, pG0, G4, HID);
    // encoder layer 0
    lstm_pass<<<128, 256, PASS_SMEM_BYTES>>>(pG0, Whh0, pZ, pZ, pY0, phe0, pce0, 0);
    // G1 = Y0 @ Wih1^T + b1
    gemm_tf32_bias<<<dim3(16, 32), 256, GEMM_SMEM_BYTES>>>(pY0, Wih1, pbc1, pG1, G4, HID);
    // encoder layer 1 (sequence output unused; dump into d_D1 scratch)
    lstm_pass<<<128, 256, PASS_SMEM_BYTES>>>(pG1, Whh1, pZ, pZ, pD1, phe1, pce1, 1);
    // latent: dh0/dh1
    latent_kernel<<<2048, 256>>>(latW, latb);
    // decoder layer 0 (reuses G0; final h/c discarded into he0/ce0)
    lstm_pass<<<128, 256, PASS_SMEM_BYTES>>>(pG0, Whh0, pdh0, pce0, pD0, phe0, pce0, 2);
    // G1d = D0 @ Wih1^T + b1
    gemm_tf32_bias<<<dim3(16, 32), 256, GEMM_SMEM_BYTES>>>(pD0, Wih1, pbc1, pG1, G4, HID);
    // decoder layer 1
    lstm_pass<<<128, 256, PASS_SMEM_BYTES>>>(pG1, Whh1, pdh1, pce1, pD1, phe1, pce1, 3);
    // logits = D1 @ emb^T + dec_bias   [2048, 32000]
    gemm_tf32_bias<<<dim3(16, 250), 256, GEMM_SMEM_BYTES>>>(pD1, emb, dec_bias, out, 32000, HID);
}

// round 5
// speedup vs baseline: 1.2940x; 1.2940x over previous
#include <cuda_runtime.h>
#include <cuda_bf16.h>
#include <cuda_pipeline.h>
#include <mma.h>
#include <cstdint>
#include <cstddef>
#include <math.h>

using namespace nvcuda;

#define S_LEN 128
#define BATCH 16
#define HID   1024
#define G4    4096
#define ROWS  2048            // S*B
#define WS_LD 1032            // padded smem leading dim
#define PASS_SMEM_BYTES ((32*WS_LD + 16*WS_LD + 8*576) * 4)   // 216576
#define GA_LD 36
#define GEMM_SMEM_BYTES (2 * 2 * 128 * GA_LD * 4)             // 73728

// ---------------- static device scratch (no cudaMalloc anywhere) -------------
__device__ __align__(16) float d_X [ROWS*HID];
__device__ __align__(16) float d_G0[ROWS*G4];
__device__ __align__(16) float d_G1[ROWS*G4];
__device__ __align__(16) float d_Y0[ROWS*HID];
__device__ __align__(16) float d_D0[ROWS*HID];
__device__ __align__(16) float d_D1[ROWS*HID];
__device__ __align__(16) float d_hbuf[2][BATCH*HID];
__device__ __align__(16) float d_he0[BATCH*HID];
__device__ __align__(16) float d_ce0[BATCH*HID];
__device__ __align__(16) float d_he1[BATCH*HID];
__device__ __align__(16) float d_ce1[BATCH*HID];
__device__ __align__(16) float d_dh0[BATCH*HID];
__device__ __align__(16) float d_dh1[BATCH*HID];
__device__ __align__(16) float d_zeros[BATCH*HID];
__device__ __align__(16) float d_bc0[G4];
__device__ __align__(16) float d_bc1[G4];
__device__ int d_done[4];

__device__ __forceinline__ float sigf(float x) { return 1.0f / (1.0f + expf(-x)); }

// ---------------- init: reset counters, combine biases, zero state -----------
__global__ void init_kernel(const float* __restrict__ bih0, const float* __restrict__ bhh0,
                            const float* __restrict__ bih1, const float* __restrict__ bhh1) {
    int tid = blockIdx.x * blockDim.x + threadIdx.x;   // 4096 threads
    if (tid < 4) d_done[tid] = 0;
    for (int i = tid; i < BATCH*HID; i += 4096) d_zeros[i] = 0.0f;
    if (tid < G4) {
        d_bc0[tid] = bih0[tid] + bhh0[tid];
        d_bc1[tid] = bih1[tid] + bhh1[tid];
    }
}

// ---------------- embedding gather -------------------------------------------
__global__ void embed_kernel(const int* __restrict__ tokens, const float* __restrict__ emb) {
    int row = blockIdx.x;                              // t*B + b
    int tok = tokens[row];
    const float4* src = (const float4*)(emb + (size_t)tok * HID);
    float4* dst = (float4*)(d_X + (size_t)row * HID);
    for (int i = threadIdx.x; i < HID/4; i += blockDim.x) dst[i] = src[i];
}

// ---------------- tf32 WMMA GEMM, cp.async 2-stage, k-tile 32 ----------------
// C[M,N] = A[M,K] @ B[N,K]^T + bias[N];  grid=(M/128,N/128), block=256
__global__ void __launch_bounds__(256) gemm_tf32_bias(
    const float* __restrict__ A, const float* __restrict__ B,
    const float* __restrict__ bias, float* __restrict__ C, int N, int K)
{
    extern __shared__ float smg[];
    const int tid = threadIdx.x;
    const int m0 = blockIdx.x * 128;
    const int n0 = blockIdx.y * 128;
    const int w  = tid >> 5;
    const int lane = tid & 31;
    const int wm = w & 3;            // 4 warps along M
    const int wn = w >> 2;           // 2 warps along N

    wmma::fragment<wmma::accumulator, 16, 16, 8, float> acc[2][4];
#pragma unroll
    for (int mi = 0; mi < 2; mi++)
#pragma unroll
        for (int nj = 0; nj < 4; nj++) wmma::fill_fragment(acc[mi][nj], 0.0f);

    const int NT = K / 32;
    // prologue: stage 0
    {
        float* As = smg;
        float* Bs = smg + 128 * GA_LD;
#pragma unroll
        for (int j = 0; j < 4; j++) {
            int idx = tid + j * 256;           // 0..1023
            int row = idx >> 3, c4 = idx & 7;
            __pipeline_memcpy_async(As + row * GA_LD + c4 * 4,
                                    A + (size_t)(m0 + row) * K + c4 * 4, 16);
            __pipeline_memcpy_async(Bs + row * GA_LD + c4 * 4,
                                    B + (size_t)(n0 + row) * K + c4 * 4, 16);
        }
        __pipeline_commit();
    }

    for (int kt = 0; kt < NT; kt++) {
        if (kt + 1 < NT) {
            float* As = smg + ((kt + 1) & 1) * 9216;
            float* Bs = As + 128 * GA_LD;
            int k0 = (kt + 1) * 32;
#pragma unroll
            for (int j = 0; j < 4; j++) {
                int idx = tid + j * 256;
                int row = idx >> 3, c4 = idx & 7;
                __pipeline_memcpy_async(As + row * GA_LD + c4 * 4,
                                        A + (size_t)(m0 + row) * K + k0 + c4 * 4, 16);
                __pipeline_memcpy_async(Bs + row * GA_LD + c4 * 4,
                                        B + (size_t)(n0 + row) * K + k0 + c4 * 4, 16);
            }
            __pipeline_commit();
            __pipeline_wait_prior(1);
        } else {
            __pipeline_wait_prior(0);
        }
        __syncthreads();
        float* As = smg + (kt & 1) * 9216;
        float* Bs = As + 128 * GA_LD;
#pragma unroll
        for (int kk = 0; kk < 32; kk += 8) {
            wmma::fragment<wmma::matrix_a, 16, 16, 8, wmma::precision::tf32, wmma::row_major> fa[2];
            wmma::fragment<wmma::matrix_b, 16, 16, 8, wmma::precision::tf32, wmma::col_major> fb[4];
#pragma unroll
            for (int mi = 0; mi < 2; mi++) {
                wmma::load_matrix_sync(fa[mi], As + (wm * 32 + mi * 16) * GA_LD + kk, GA_LD);
#pragma unroll
                for (int e = 0; e < fa[mi].num_elements; e++)
                    fa[mi].x[e] = wmma::__float_to_tf32(fa[mi].x[e]);
            }
#pragma unroll
            for (int nj = 0; nj < 4; nj++) {
                wmma::load_matrix_sync(fb[nj], Bs + (wn * 64 + nj * 16) * GA_LD + kk, GA_LD);
#pragma unroll
                for (int e = 0; e < fb[nj].num_elements; e++)
                    fb[nj].x[e] = wmma::__float_to_tf32(fb[nj].x[e]);
            }
#pragma unroll
            for (int mi = 0; mi < 2; mi++)
#pragma unroll
                for (int nj = 0; nj < 4; nj++)
                    wmma::mma_sync(acc[mi][nj], fa[mi], fb[nj], acc[mi][nj]);
        }
        __syncthreads();
    }

    // epilogue: per-warp smem buffer (overlays stages), bias add, coalesced stores
    float* myb = smg + w * 2048;
#pragma unroll
    for (int mi = 0; mi < 2; mi++)
#pragma unroll
        for (int nj = 0; nj < 4; nj++)
            wmma::store_matrix_sync(myb + mi * 1024 + nj * 16, acc[mi][nj], 64, wmma::mem_row_major);
    __syncwarp();
#pragma unroll 8
    for (int i = 0; i < 64; i++) {
        int idx = i * 32 + lane;       // 0..2047
        int r = idx >> 6;              // 0..31
        int c = idx & 63;              // 0..63
        float v = myb[r * 64 + c] + bias[n0 + wn * 64 + c];
        C[(size_t)(m0 + wm * 32 + r) * N + n0 + wn * 64 + c] = v;
    }
}

// ---------------- persistent LSTM layer pass (1 grid sync per step) ----------
// 128 CTAs, 1/SM, co-resident (216.6KB smem each). CTA n owns hidden units
// [8n,8n+8) and ALL FOUR gates for them (32 Whh rows resident in smem for all
// 128 steps). Cell state lives in registers; h broadcast via L2 double buffer.
__global__ void __launch_bounds__(256, 1) lstm_pass(
    const float* __restrict__ Gpre, const float* __restrict__ Whh,
    const float* __restrict__ h0, const float* __restrict__ c0,
    float* __restrict__ y, float* __restrict__ hout, float* __restrict__ cout, int pass)
{
    extern __shared__ float sm[];
    float* ws  = sm;                       // [32][WS_LD] weights (tf32-rounded)
    float* hs  = sm + 32 * WS_LD;          // [16][WS_LD] h staging
    float* red = sm + 48 * WS_LD;          // 8 warps x [16][36]
    const int tid = threadIdx.x;
    const int cta = blockIdx.x;
    const int w   = tid >> 5;

    // weight slice: smem row r = gate(r>>3), unit(r&7); global row g*HID + 8*cta + du
    for (int i = tid; i < 32 * 256; i += 256) {
        int r = i >> 8, c = i & 255;
        int grow = (r >> 3) * HID + cta * 8 + (r & 7);
        float4 v = __ldg((const float4*)(Whh + (size_t)grow * HID) + c);
        v.x = wmma::__float_to_tf32(v.x); v.y = wmma::__float_to_tf32(v.y);
        v.z = wmma::__float_to_tf32(v.z); v.w = wmma::__float_to_tf32(v.w);
        ((float4*)(ws + r * WS_LD))[c] = v;
    }
    __syncthreads();

    volatile int* vd = (volatile int*)&d_done[pass];
    const int b  = tid >> 3;               // valid for tid<128
    const int du = tid & 7;
    const int j  = cta * 8 + du;
    float creg = 0.0f;
    if (tid < 128) creg = c0[b * HID + j];

#pragma unroll 1
    for (int t = 0; t < S_LEN; t++) {
        // prefetch input-projection gates (independent of h) before the spin
        float gp0 = 0.f, gp1 = 0.f, gp2 = 0.f, gp3 = 0.f;
        if (tid < 128) {
            const float* g = Gpre + (size_t)t * BATCH * G4 + b * G4 + j;
            gp0 = __ldg(g); gp1 = __ldg(g + HID); gp2 = __ldg(g + 2*HID); gp3 = __ldg(g + 3*HID);
        }
        if (t > 0) {
            if (tid == 0) { while (*vd < 128 * t) { __nanosleep(40); } }
        }
        __syncthreads();

        // stage h[t-1] (L2-coherent reads), round to tf32
        {
            const float4* src = (t == 0) ? (const float4*)h0
                                         : (const float4*)d_hbuf[(t + 1) & 1];
#pragma unroll
            for (int q = 0; q < 16; q++) {
                int i = tid + q * 256;         // 0..4095
                float4 v = __ldcg(src + i);
                v.x = wmma::__float_to_tf32(v.x); v.y = wmma::__float_to_tf32(v.y);
                v.z = wmma::__float_to_tf32(v.z); v.w = wmma::__float_to_tf32(v.w);
                ((float4*)(hs + (i >> 8) * WS_LD))[i & 255] = v;
            }
        }
        __syncthreads();

        // 16x32x1024 matmul, K split across 8 warps
        {
            wmma::fragment<wmma::accumulator, 16, 16, 8, float> a0, a1;
            wmma::fill_fragment(a0, 0.0f);
            wmma::fill_fragment(a1, 0.0f);
#pragma unroll
            for (int kk = 0; kk < 128; kk += 8) {
                int k = w * 128 + kk;
                wmma::fragment<wmma::matrix_a, 16, 16, 8, wmma::precision::tf32, wmma::row_major> fa;
                wmma::fragment<wmma::matrix_b, 16, 16, 8, wmma::precision::tf32, wmma::col_major> f0, f1;
                wmma::load_matrix_sync(fa, hs + k, WS_LD);
                wmma::load_matrix_sync(f0, ws + k, WS_LD);
                wmma::load_matrix_sync(f1, ws + 16 * WS_LD + k, WS_LD);
                wmma::mma_sync(a0, fa, f0, a0);
                wmma::mma_sync(a1, fa, f1, a1);
            }
            wmma::store_matrix_sync(red + w * 576,      a0, 36, wmma::mem_row_major);
            wmma::store_matrix_sync(red + w * 576 + 16, a1, 36, wmma::mem_row_major);
        }
        __syncthreads();

        // reduce partials, apply LSTM elementwise locally (CTA owns all 4 gates)
        if (tid < 128) {
            float s0 = gp0, s1 = gp1, s2 = gp2, s3 = gp3;
#pragma unroll
            for (int p = 0; p < 8; p++) {
                const float* rp = red + p * 576 + b * 36;
                s0 += rp[du]; s1 += rp[8 + du]; s2 += rp[16 + du]; s3 += rp[24 + du];
            }
            float c = sigf(s1) * creg + sigf(s0) * tanhf(s2);
            float h = sigf(s3) * tanhf(c);
            creg = c;
            d_hbuf[t & 1][b * HID + j] = h;
            y[(size_t)t * BATCH * HID + b * HID + j] = h;
            if (t == S_LEN - 1) { hout[b * HID + j] = h; cout[b * HID + j] = c; }
        }
        __threadfence();
        __syncthreads();
        if (tid == 0) atomicAdd(&d_done[pass], 1);
    }
}

// ---------------- latent linear: dh = he @ latW^T + latb (fp32 exact) --------
__global__ void latent_kernel(const float* __restrict__ latW, const float* __restrict__ latb) {
    __shared__ float hesh[HID];
    int blk = blockIdx.x;
    int which = blk >> 10;
    int rem = blk & 1023;
    int b = rem >> 6;
    int jg = rem & 63;
    const float* he = which ? d_he1 : d_he0;
    float* dh = which ? d_dh1 : d_dh0;
    for (int i = threadIdx.x; i < HID; i += 256) hesh[i] = he[b * HID + i];
    __syncthreads();
    int w = threadIdx.x >> 5, lane = threadIdx.x & 31;
#pragma unroll
    for (int q = 0; q < 2; q++) {
        int j = jg * 16 + w * 2 + q;
        const float* wr = latW + (size_t)j * HID;
        float s = 0.0f;
        for (int k = lane; k < HID; k += 32) s += wr[k] * hesh[k];
#pragma unroll
        for (int o = 16; o; o >>= 1) s += __shfl_xor_sync(0xFFFFFFFFu, s, o);
        if (lane == 0) dh[b * HID + j] = s + latb[j];
    }
}

// ---------------- host orchestration -----------------------------------------
extern "C" void kernel_launch(void* const* d_in, const int* in_sizes, int n_in,
                              void* d_out, int out_size) {
    const int*   tokens   = (const int*)  d_in[0];
    const float* emb      = (const float*)d_in[1];
    const float* dec_bias = (const float*)d_in[2];
    const float* Wih0     = (const float*)d_in[3];
    const float* Whh0     = (const float*)d_in[4];
    const float* bih0     = (const float*)d_in[5];
    const float* bhh0     = (const float*)d_in[6];
    const float* Wih1     = (const float*)d_in[7];
    const float* Whh1     = (const float*)d_in[8];
    const float* bih1     = (const float*)d_in[9];
    const float* bhh1     = (const float*)d_in[10];
    const float* latW     = (const float*)d_in[11];
    const float* latb     = (const float*)d_in[12];
    float* out = (float*)d_out;

    cudaFuncSetAttribute(gemm_tf32_bias, cudaFuncAttributeMaxDynamicSharedMemorySize, GEMM_SMEM_BYTES);
    cudaFuncSetAttribute(lstm_pass,      cudaFuncAttributeMaxDynamicSharedMemorySize, PASS_SMEM_BYTES);

    float *pX, *pG0, *pG1, *pY0, *pD0, *pD1, *pZ, *pbc0, *pbc1;
    float *phe0, *pce0, *phe1, *pce1, *pdh0, *pdh1;
    cudaGetSymbolAddress((void**)&pX,   d_X);
    cudaGetSymbolAddress((void**)&pG0,  d_G0);
    cudaGetSymbolAddress((void**)&pG1,  d_G1);
    cudaGetSymbolAddress((void**)&pY0,  d_Y0);
    cudaGetSymbolAddress((void**)&pD0,  d_D0);
    cudaGetSymbolAddress((void**)&pD1,  d_D1);
    cudaGetSymbolAddress((void**)&pZ,   d_zeros);
    cudaGetSymbolAddress((void**)&pbc0, d_bc0);
    cudaGetSymbolAddress((void**)&pbc1, d_bc1);
    cudaGetSymbolAddress((void**)&phe0, d_he0);
    cudaGetSymbolAddress((void**)&pce0, d_ce0);
    cudaGetSymbolAddress((void**)&phe1, d_he1);
    cudaGetSymbolAddress((void**)&pce1, d_ce1);
    cudaGetSymbolAddress((void**)&pdh0, d_dh0);
    cudaGetSymbolAddress((void**)&pdh1, d_dh1);

    init_kernel<<<16, 256>>>(bih0, bhh0, bih1, bhh1);
    embed_kernel<<<ROWS, 256>>>(tokens, emb);

    // G0 = X @ Wih0^T + (bih0+bhh0)  (shared by enc-l0 and teacher-forced dec-l0)
    gemm_tf32_bias<<<dim3(16, 32), 256, GEMM_SMEM_BYTES>>>(pX, Wih0, pbc0, pG0, G4, HID);
    // encoder layer 0
    lstm_pass<<<128, 256, PASS_SMEM_BYTES>>>(pG0, Whh0, pZ, pZ, pY0, phe0, pce0, 0);
    // G1 = Y0 @ Wih1^T + b1
    gemm_tf32_bias<<<dim3(16, 32), 256, GEMM_SMEM_BYTES>>>(pY0, Wih1, pbc1, pG1, G4, HID);
    // encoder layer 1 (sequence output unused; dumped into d_D1 scratch)
    lstm_pass<<<128, 256, PASS_SMEM_BYTES>>>(pG1, Whh1, pZ, pZ, pD1, phe1, pce1, 1);
    // latent transforms
    latent_kernel<<<2048, 256>>>(latW, latb);
    // decoder layer 0 (reuses G0; final h/c discarded into he0/ce0)
    lstm_pass<<<128, 256, PASS_SMEM_BYTES>>>(pG0, Whh0, pdh0, pce0, pD0, phe0, pce0, 2);
    // G1d = D0 @ Wih1^T + b1
    gemm_tf32_bias<<<dim3(16, 32), 256, GEMM_SMEM_BYTES>>>(pD0, Wih1, pbc1, pG1, G4, HID);
    // decoder layer 1
    lstm_pass<<<128, 256, PASS_SMEM_BYTES>>>(pG1, Whh1, pdh1, pce1, pD1, phe1, pce1, 3);
    // logits = D1 @ emb^T + dec_bias   [2048, 32000]
    gemm_tf32_bias<<<dim3(16, 250), 256, GEMM_SMEM_BYTES>>>(pD1, emb, dec_bias, out, 32000, HID);
}

// round 6
// speedup vs baseline: 1.3768x; 1.0640x over previous
#include <cuda_runtime.h>
#include <cuda_bf16.h>
#include <cuda_pipeline.h>
#include <mma.h>
#include <cstdint>
#include <cstddef>
#include <math.h>

using namespace nvcuda;

#define S_LEN 128
#define BATCH 16
#define HID   1024
#define G4    4096
#define ROWS  2048            // S*B
#define WS_LD 1032            // padded smem leading dim (lstm)
#define PASS_SMEM_BYTES ((32*WS_LD + 16*WS_LD + 8*576) * 4)   // 216576
#define GM_LD 36              // gemm smem row pad (floats)
#define GM_STAGE_FLOATS ((128 + 256) * GM_LD)                 // 13824
#define GEMM_SMEM_BYTES (2 * GM_STAGE_FLOATS * 4)             // 110592

// ---------------- static device scratch (no cudaMalloc anywhere) -------------
__device__ __align__(16) float d_X [ROWS*HID];
__device__ __align__(16) float d_G0[ROWS*G4];
__device__ __align__(16) float d_G1[ROWS*G4];
__device__ __align__(16) float d_Y0[ROWS*HID];
__device__ __align__(16) float d_D0[ROWS*HID];
__device__ __align__(16) float d_D1[ROWS*HID];
__device__ __align__(16) float d_hbuf[2][BATCH*HID];
__device__ __align__(16) float d_he0[BATCH*HID];
__device__ __align__(16) float d_ce0[BATCH*HID];
__device__ __align__(16) float d_he1[BATCH*HID];
__device__ __align__(16) float d_ce1[BATCH*HID];
__device__ __align__(16) float d_dh0[BATCH*HID];
__device__ __align__(16) float d_dh1[BATCH*HID];
__device__ __align__(16) float d_zeros[BATCH*HID];
__device__ __align__(16) float d_bc0[G4];
__device__ __align__(16) float d_bc1[G4];
__device__ int d_done[4];

__device__ __forceinline__ float sigf(float x) { return 1.0f / (1.0f + expf(-x)); }

// ---------------- init: reset counters, combine biases, zero state -----------
__global__ void init_kernel(const float* __restrict__ bih0, const float* __restrict__ bhh0,
                            const float* __restrict__ bih1, const float* __restrict__ bhh1) {
    int tid = blockIdx.x * blockDim.x + threadIdx.x;   // 4096 threads
    if (tid < 4) d_done[tid] = 0;
    for (int i = tid; i < BATCH*HID; i += 4096) d_zeros[i] = 0.0f;
    if (tid < G4) {
        d_bc0[tid] = bih0[tid] + bhh0[tid];
        d_bc1[tid] = bih1[tid] + bhh1[tid];
    }
}

// ---------------- embedding gather -------------------------------------------
__global__ void embed_kernel(const int* __restrict__ tokens, const float* __restrict__ emb) {
    int row = blockIdx.x;                              // t*B + b
    int tok = tokens[row];
    const float4* src = (const float4*)(emb + (size_t)tok * HID);
    float4* dst = (float4*)(d_X + (size_t)row * HID);
    for (int i = threadIdx.x; i < HID/4; i += blockDim.x) dst[i] = src[i];
}

// ---------------- tf32 WMMA GEMM: CTA 128x256, warp 64x64, 2-stage cp.async --
// C[M,N] = A[M,K] @ B[N,K]^T + bias[N];  grid=(M/128, N/256), block=256
__global__ void __launch_bounds__(256) gemm_tf32_bias(
    const float* __restrict__ A, const float* __restrict__ B,
    const float* __restrict__ bias, float* __restrict__ C, int N, int K)
{
    extern __shared__ float smg[];
    const int tid = threadIdx.x;
    const int m0 = blockIdx.x * 128;
    const int n0 = blockIdx.y * 256;
    const int w  = tid >> 5;
    const int lane = tid & 31;
    const int wm = w & 1;            // 2 warps along M
    const int wn = w >> 1;           // 4 warps along N

    wmma::fragment<wmma::accumulator, 16, 16, 8, float> acc[4][4];
#pragma unroll
    for (int mi = 0; mi < 4; mi++)
#pragma unroll
        for (int nj = 0; nj < 4; nj++) wmma::fill_fragment(acc[mi][nj], 0.0f);

    const int NT = K / 32;

    // async stage loader: A 128 rows, B 256 rows, 8 float4 per row
    auto load_stage = [&](int s, int k0) {
        float* As = smg + s * GM_STAGE_FLOATS;
        float* Bs = As + 128 * GM_LD;
#pragma unroll
        for (int j = 0; j < 4; j++) {
            int idx = tid + j * 256;           // 0..1023
            int row = idx >> 3, c4 = idx & 7;
            __pipeline_memcpy_async(As + row * GM_LD + c4 * 4,
                                    A + (size_t)(m0 + row) * K + k0 + c4 * 4, 16);
        }
#pragma unroll
        for (int j = 0; j < 8; j++) {
            int idx = tid + j * 256;           // 0..2047
            int row = idx >> 3, c4 = idx & 7;
            __pipeline_memcpy_async(Bs + row * GM_LD + c4 * 4,
                                    B + (size_t)(n0 + row) * K + k0 + c4 * 4, 16);
        }
        __pipeline_commit();
    };

    load_stage(0, 0);

    for (int kt = 0; kt < NT; kt++) {
        if (kt + 1 < NT) {
            load_stage((kt + 1) & 1, (kt + 1) * 32);
            __pipeline_wait_prior(1);
        } else {
            __pipeline_wait_prior(0);
        }
        __syncthreads();
        float* As = smg + (kt & 1) * GM_STAGE_FLOATS;
        float* Bs = As + 128 * GM_LD;
#pragma unroll
        for (int kk = 0; kk < 32; kk += 8) {
            wmma::fragment<wmma::matrix_a, 16, 16, 8, wmma::precision::tf32, wmma::row_major> fa[4];
            wmma::fragment<wmma::matrix_b, 16, 16, 8, wmma::precision::tf32, wmma::col_major> fb[4];
#pragma unroll
            for (int mi = 0; mi < 4; mi++) {
                wmma::load_matrix_sync(fa[mi], As + (wm * 64 + mi * 16) * GM_LD + kk, GM_LD);
#pragma unroll
                for (int e = 0; e < fa[mi].num_elements; e++)
                    fa[mi].x[e] = wmma::__float_to_tf32(fa[mi].x[e]);
            }
#pragma unroll
            for (int nj = 0; nj < 4; nj++) {
                wmma::load_matrix_sync(fb[nj], Bs + (wn * 64 + nj * 16) * GM_LD + kk, GM_LD);
#pragma unroll
                for (int e = 0; e < fb[nj].num_elements; e++)
                    fb[nj].x[e] = wmma::__float_to_tf32(fb[nj].x[e]);
            }
#pragma unroll
            for (int mi = 0; mi < 4; mi++)
#pragma unroll
                for (int nj = 0; nj < 4; nj++)
                    wmma::mma_sync(acc[mi][nj], fa[mi], fb[nj], acc[mi][nj]);
        }
        __syncthreads();
    }
    __syncthreads();   // all mma done before epilogue overlays stage smem

    // epilogue: per-warp private 16x64 slab, bias add, coalesced global stores
    float* slab = smg + w * 1024;
#pragma unroll
    for (int mi = 0; mi < 4; mi++) {
#pragma unroll
        for (int nj = 0; nj < 4; nj++)
            wmma::store_matrix_sync(slab + nj * 16, acc[mi][nj], 64, wmma::mem_row_major);
        __syncwarp();
#pragma unroll 4
        for (int i = 0; i < 32; i++) {
            int idx = i * 32 + lane;       // 0..1023
            int r = idx >> 6;              // 0..15
            int c = idx & 63;              // 0..63
            float v = slab[r * 64 + c] + __ldg(&bias[n0 + wn * 64 + c]);
            C[(size_t)(m0 + wm * 64 + mi * 16 + r) * N + n0 + wn * 64 + c] = v;
        }
        __syncwarp();
    }
}

// ---------------- persistent LSTM layer pass (1 grid sync per step) ----------
// 128 CTAs, 1/SM, co-resident (216.6KB smem each). CTA n owns hidden units
// [8n,8n+8) and ALL FOUR gates for them (32 Whh rows resident in smem for all
// 128 steps). Cell state lives in registers; h broadcast via L2 double buffer.
__global__ void __launch_bounds__(256, 1) lstm_pass(
    const float* __restrict__ Gpre, const float* __restrict__ Whh,
    const float* __restrict__ h0, const float* __restrict__ c0,
    float* __restrict__ y, float* __restrict__ hout, float* __restrict__ cout, int pass)
{
    extern __shared__ float sm[];
    float* ws  = sm;                       // [32][WS_LD] weights (tf32-rounded)
    float* hs  = sm + 32 * WS_LD;          // [16][WS_LD] h staging
    float* red = sm + 48 * WS_LD;          // 8 warps x [16][36]
    const int tid = threadIdx.x;
    const int cta = blockIdx.x;
    const int w   = tid >> 5;

    // weight slice: smem row r = gate(r>>3), unit(r&7); global row g*HID + 8*cta + du
    for (int i = tid; i < 32 * 256; i += 256) {
        int r = i >> 8, c = i & 255;
        int grow = (r >> 3) * HID + cta * 8 + (r & 7);
        float4 v = __ldg((const float4*)(Whh + (size_t)grow * HID) + c);
        v.x = wmma::__float_to_tf32(v.x); v.y = wmma::__float_to_tf32(v.y);
        v.z = wmma::__float_to_tf32(v.z); v.w = wmma::__float_to_tf32(v.w);
        ((float4*)(ws + r * WS_LD))[c] = v;
    }
    __syncthreads();

    volatile int* vd = (volatile int*)&d_done[pass];
    const int b  = tid >> 3;               // valid for tid<128
    const int du = tid & 7;
    const int j  = cta * 8 + du;
    float creg = 0.0f;
    if (tid < 128) creg = c0[b * HID + j];

#pragma unroll 1
    for (int t = 0; t < S_LEN; t++) {
        // prefetch input-projection gates (independent of h) before the spin
        float gp0 = 0.f, gp1 = 0.f, gp2 = 0.f, gp3 = 0.f;
        if (tid < 128) {
            const float* g = Gpre + (size_t)t * BATCH * G4 + b * G4 + j;
            gp0 = __ldg(g); gp1 = __ldg(g + HID); gp2 = __ldg(g + 2*HID); gp3 = __ldg(g + 3*HID);
        }
        if (t > 0) {
            if (tid == 0) { while (*vd < 128 * t) { } }
        }
        __syncthreads();

        // stage h[t-1] (L2-coherent reads), round to tf32
        {
            const float4* src = (t == 0) ? (const float4*)h0
                                         : (const float4*)d_hbuf[(t + 1) & 1];
#pragma unroll
            for (int q = 0; q < 16; q++) {
                int i = tid + q * 256;         // 0..4095
                float4 v = __ldcg(src + i);
                v.x = wmma::__float_to_tf32(v.x); v.y = wmma::__float_to_tf32(v.y);
                v.z = wmma::__float_to_tf32(v.z); v.w = wmma::__float_to_tf32(v.w);
                ((float4*)(hs + (i >> 8) * WS_LD))[i & 255] = v;
            }
        }
        __syncthreads();

        // 16x32x1024 matmul, K split across 8 warps
        {
            wmma::fragment<wmma::accumulator, 16, 16, 8, float> a0, a1;
            wmma::fill_fragment(a0, 0.0f);
            wmma::fill_fragment(a1, 0.0f);
#pragma unroll
            for (int kk = 0; kk < 128; kk += 8) {
                int k = w * 128 + kk;
                wmma::fragment<wmma::matrix_a, 16, 16, 8, wmma::precision::tf32, wmma::row_major> fa;
                wmma::fragment<wmma::matrix_b, 16, 16, 8, wmma::precision::tf32, wmma::col_major> f0, f1;
                wmma::load_matrix_sync(fa, hs + k, WS_LD);
                wmma::load_matrix_sync(f0, ws + k, WS_LD);
                wmma::load_matrix_sync(f1, ws + 16 * WS_LD + k, WS_LD);
                wmma::mma_sync(a0, fa, f0, a0);
                wmma::mma_sync(a1, fa, f1, a1);
            }
            wmma::store_matrix_sync(red + w * 576,      a0, 36, wmma::mem_row_major);
            wmma::store_matrix_sync(red + w * 576 + 16, a1, 36, wmma::mem_row_major);
        }
        __syncthreads();

        // reduce partials, apply LSTM elementwise locally (CTA owns all 4 gates)
        if (tid < 128) {
            float s0 = gp0, s1 = gp1, s2 = gp2, s3 = gp3;
#pragma unroll
            for (int p = 0; p < 8; p++) {
                const float* rp = red + p * 576 + b * 36;
                s0 += rp[du]; s1 += rp[8 + du]; s2 += rp[16 + du]; s3 += rp[24 + du];
            }
            float c = sigf(s1) * creg + sigf(s0) * tanhf(s2);
            float h = sigf(s3) * tanhf(c);
            creg = c;
            d_hbuf[t & 1][b * HID + j] = h;
            y[(size_t)t * BATCH * HID + b * HID + j] = h;
            if (t == S_LEN - 1) { hout[b * HID + j] = h; cout[b * HID + j] = c; }
        }
        __threadfence();
        __syncthreads();
        if (tid == 0) atomicAdd(&d_done[pass], 1);
    }
}

// ---------------- latent linear: dh = he @ latW^T + latb (fp32 exact) --------
__global__ void latent_kernel(const float* __restrict__ latW, const float* __restrict__ latb) {
    __shared__ float hesh[HID];
    int blk = blockIdx.x;
    int which = blk >> 10;
    int rem = blk & 1023;
    int b = rem >> 6;
    int jg = rem & 63;
    const float* he = which ? d_he1 : d_he0;
    float* dh = which ? d_dh1 : d_dh0;
    for (int i = threadIdx.x; i < HID; i += 256) hesh[i] = he[b * HID + i];
    __syncthreads();
    int w = threadIdx.x >> 5, lane = threadIdx.x & 31;
#pragma unroll
    for (int q = 0; q < 2; q++) {
        int j = jg * 16 + w * 2 + q;
        const float* wr = latW + (size_t)j * HID;
        float s = 0.0f;
        for (int k = lane; k < HID; k += 32) s += wr[k] * hesh[k];
#pragma unroll
        for (int o = 16; o; o >>= 1) s += __shfl_xor_sync(0xFFFFFFFFu, s, o);
        if (lane == 0) dh[b * HID + j] = s + latb[j];
    }
}

// ---------------- host orchestration -----------------------------------------
extern "C" void kernel_launch(void* const* d_in, const int* in_sizes, int n_in,
                              void* d_out, int out_size) {
    const int*   tokens   = (const int*)  d_in[0];
    const float* emb      = (const float*)d_in[1];
    const float* dec_bias = (const float*)d_in[2];
    const float* Wih0     = (const float*)d_in[3];
    const float* Whh0     = (const float*)d_in[4];
    const float* bih0     = (const float*)d_in[5];
    const float* bhh0     = (const float*)d_in[6];
    const float* Wih1     = (const float*)d_in[7];
    const float* Whh1     = (const float*)d_in[8];
    const float* bih1     = (const float*)d_in[9];
    const float* bhh1     = (const float*)d_in[10];
    const float* latW     = (const float*)d_in[11];
    const float* latb     = (const float*)d_in[12];
    float* out = (float*)d_out;

    cudaFuncSetAttribute(gemm_tf32_bias, cudaFuncAttributeMaxDynamicSharedMemorySize, GEMM_SMEM_BYTES);
    cudaFuncSetAttribute(lstm_pass,      cudaFuncAttributeMaxDynamicSharedMemorySize, PASS_SMEM_BYTES);

    float *pX, *pG0, *pG1, *pY0, *pD0, *pD1, *pZ, *pbc0, *pbc1;
    float *phe0, *pce0, *phe1, *pce1, *pdh0, *pdh1;
    cudaGetSymbolAddress((void**)&pX,   d_X);
    cudaGetSymbolAddress((void**)&pG0,  d_G0);
    cudaGetSymbolAddress((void**)&pG1,  d_G1);
    cudaGetSymbolAddress((void**)&pY0,  d_Y0);
    cudaGetSymbolAddress((void**)&pD0,  d_D0);
    cudaGetSymbolAddress((void**)&pD1,  d_D1);
    cudaGetSymbolAddress((void**)&pZ,   d_zeros);
    cudaGetSymbolAddress((void**)&pbc0, d_bc0);
    cudaGetSymbolAddress((void**)&pbc1, d_bc1);
    cudaGetSymbolAddress((void**)&phe0, d_he0);
    cudaGetSymbolAddress((void**)&pce0, d_ce0);
    cudaGetSymbolAddress((void**)&phe1, d_he1);
    cudaGetSymbolAddress((void**)&pce1, d_ce1);
    cudaGetSymbolAddress((void**)&pdh0, d_dh0);
    cudaGetSymbolAddress((void**)&pdh1, d_dh1);

    init_kernel<<<16, 256>>>(bih0, bhh0, bih1, bhh1);
    embed_kernel<<<ROWS, 256>>>(tokens, emb);

    // G0 = X @ Wih0^T + (bih0+bhh0)  (shared by enc-l0 and teacher-forced dec-l0)
    gemm_tf32_bias<<<dim3(16, 16), 256, GEMM_SMEM_BYTES>>>(pX, Wih0, pbc0, pG0, G4, HID);
    // encoder layer 0
    lstm_pass<<<128, 256, PASS_SMEM_BYTES>>>(pG0, Whh0, pZ, pZ, pY0, phe0, pce0, 0);
    // G1 = Y0 @ Wih1^T + b1
    gemm_tf32_bias<<<dim3(16, 16), 256, GEMM_SMEM_BYTES>>>(pY0, Wih1, pbc1, pG1, G4, HID);
    // encoder layer 1 (sequence output unused; dumped into d_D1 scratch)
    lstm_pass<<<128, 256, PASS_SMEM_BYTES>>>(pG1, Whh1, pZ, pZ, pD1, phe1, pce1, 1);
    // latent transforms
    latent_kernel<<<2048, 256>>>(latW, latb);
    // decoder layer 0 (reuses G0; final h/c discarded into he0/ce0)
    lstm_pass<<<128, 256, PASS_SMEM_BYTES>>>(pG0, Whh0, pdh0, pce0, pD0, phe0, pce0, 2);
    // G1d = D0 @ Wih1^T + b1
    gemm_tf32_bias<<<dim3(16, 16), 256, GEMM_SMEM_BYTES>>>(pD0, Wih1, pbc1, pG1, G4, HID);
    // decoder layer 1
    lstm_pass<<<128, 256, PASS_SMEM_BYTES>>>(pG1, Whh1, pdh1, pce1, pD1, phe1, pce1, 3);
    // logits = D1 @ emb^T + dec_bias   [2048, 32000]
    gemm_tf32_bias<<<dim3(16, 125), 256, GEMM_SMEM_BYTES>>>(pD1, emb, dec_bias, out, 32000, HID);
}